// round 8
// baseline (speedup 1.0000x reference)
#include <cuda_runtime.h>
#include <math.h>

#define BGRAPHS 512
#define MNODES  200
#define EPG     6400
#define ETOT    3276800
#define NTHREADS 1024
#define NW 32

// ---- shared memory layout (float slots) ----
#define OFF_HCAT   0          // 200*100 = 20000 (also x@W1 per-warp scratch early)
#define OFF_XW     20000      // 200*32  = 6400   (holds dinv-scaled xw)
#define OFF_SW     26400      // 4224 weight/scratch staging (W1^T = 32*132)
#define OFF_DINV   30624      // 200
#define OFF_ROWPTR 30824      // 204 ints
#define OFF_FILL   31028      // 200 ints
#define OFF_DEGI   31228      // 200 ints
#define OFF_CSRSRC 31428      // 6400 u16 -> 3200 slots
#define OFF_SRC16  34628      // 6400 u16 -> 3200 slots
#define OFF_DST16  37828      // 6400 u16 -> 3200 slots
#define OFF_KEY    41028      // 200
#define OFF_SEL    41228      // 32 ints
#define OFF_C1     41260      // 480
#define OFF_POOL   41740      // 240
#define OFF_FLAT   41980      // 352
#define OFF_HLIN   42332      // 128
#define SMEM_SLOTS 42460
#define SMEM_BYTES (SMEM_SLOTS * 4)

typedef unsigned long long u64;

__device__ __forceinline__ u64 fma2(u64 a, u64 b, u64 c) {
    u64 d; asm("fma.rn.f32x2 %0,%1,%2,%3;" : "=l"(d) : "l"(a), "l"(b), "l"(c)); return d;
}
__device__ __forceinline__ u64 add2(u64 a, u64 b) {
    u64 d; asm("add.rn.f32x2 %0,%1,%2;" : "=l"(d) : "l"(a), "l"(b)); return d;
}
__device__ __forceinline__ float2 u2f(u64 a) {
    float2 f; asm("mov.b64 {%0,%1},%2;" : "=f"(f.x), "=f"(f.y) : "l"(a)); return f;
}

__device__ __forceinline__ float warp_sum(float v) {
    #pragma unroll
    for (int o = 16; o > 0; o >>= 1) v += __shfl_down_sync(0xffffffffu, v, o);
    return v;
}

__device__ __forceinline__ float fast_tanh(float x) {
    float xc = fminf(fmaxf(x, -15.0f), 15.0f);
    float t = __expf(2.0f * xc);
    return __fdividef(t - 1.0f, t + 1.0f);
}

__global__ __launch_bounds__(NTHREADS, 1)
void dgcnn_kernel(
    const float* __restrict__ x, const int* __restrict__ ei,
    const float* __restrict__ W1, const float* __restrict__ b1,
    const float* __restrict__ W2, const float* __restrict__ b2,
    const float* __restrict__ W3, const float* __restrict__ b3,
    const float* __restrict__ W4, const float* __restrict__ b4,
    const float* __restrict__ convW1, const float* __restrict__ convb1,
    const float* __restrict__ convW2, const float* __restrict__ convb2,
    const float* __restrict__ linW1, const float* __restrict__ linb1,
    const float* __restrict__ linW2, const float* __restrict__ linb2,
    float* __restrict__ out)
{
    extern __shared__ float smem[];
    float* hcat   = smem + OFF_HCAT;    // [200][100]
    float* xw     = smem + OFF_XW;      // [200][32] (dinv-scaled)
    float* sW     = smem + OFF_SW;      // transposed weight staging / scratch
    float* dinv   = smem + OFF_DINV;
    int*   rowptr = (int*)(smem + OFF_ROWPTR);
    int*   fill   = (int*)(smem + OFF_FILL);
    int*   degi   = (int*)(smem + OFF_DEGI);
    unsigned short* csrsrc = (unsigned short*)(smem + OFF_CSRSRC);
    unsigned short* src16  = (unsigned short*)(smem + OFF_SRC16);
    unsigned short* dst16  = (unsigned short*)(smem + OFF_DST16);
    float* sKey   = smem + OFF_KEY;
    int*   sSel   = (int*)(smem + OFF_SEL);
    float* sC1    = smem + OFF_C1;
    float* sPool  = smem + OFF_POOL;
    float* sFlat  = smem + OFF_FLAT;
    float* sHlin  = smem + OFF_HLIN;

    const int g    = blockIdx.x;
    const int tid  = threadIdx.x;
    const int lane = tid & 31;
    const int warp = tid >> 5;
    const int half = lane >> 4;      // 0/1: which node of the pair (gather)
    const int hl   = lane & 15;      // feature-pair index within node
    const int nbase = g * MNODES;
    const long ebase = (long)g * EPG;
    const int* srcg = ei + ebase;
    const int* dstg = ei + (long)ETOT + ebase;

    // ---------------- Phase A: degrees + local edge staging (vectorized) ----------------
    for (int i = tid; i < MNODES; i += NTHREADS) degi[i] = 0;
    __syncthreads();
    for (int i = tid; i < EPG / 4; i += NTHREADS) {
        int4 s4 = ((const int4*)srcg)[i];
        int4 d4 = ((const int4*)dstg)[i];
        ushort4 ss, dd;
        ss.x = (unsigned short)(s4.x - nbase); ss.y = (unsigned short)(s4.y - nbase);
        ss.z = (unsigned short)(s4.z - nbase); ss.w = (unsigned short)(s4.w - nbase);
        dd.x = (unsigned short)(d4.x - nbase); dd.y = (unsigned short)(d4.y - nbase);
        dd.z = (unsigned short)(d4.z - nbase); dd.w = (unsigned short)(d4.w - nbase);
        ((ushort4*)src16)[i] = ss;
        ((ushort4*)dst16)[i] = dd;
        atomicAdd(&degi[dd.x], 1); atomicAdd(&degi[dd.y], 1);
        atomicAdd(&degi[dd.z], 1); atomicAdd(&degi[dd.w], 1);
    }
    __syncthreads();
    for (int i = tid; i < MNODES; i += NTHREADS) {
        dinv[i] = rsqrtf((float)degi[i] + 1.0f);
        fill[i] = 0;
    }
    if (warp == 0) {
        int run = 0;
        #pragma unroll
        for (int c = 0; c < 7; ++c) {
            int i = c * 32 + lane;
            int dv = (i < MNODES) ? degi[i] : 0;
            int v = dv;
            #pragma unroll
            for (int o = 1; o < 32; o <<= 1) {
                int t = __shfl_up_sync(0xffffffffu, v, o);
                if (lane >= o) v += t;
            }
            if (i < MNODES) rowptr[i] = run + v - dv;
            run += __shfl_sync(0xffffffffu, v, 31);
        }
        if (lane == 0) rowptr[MNODES] = EPG;
    }
    __syncthreads();
    // CSR scatter; stage W1^T concurrently: sW[c*132 + k] = W1[k*32 + c]
    for (int i = tid; i < EPG; i += NTHREADS) {
        int d = dst16[i];
        int pos = rowptr[d] + atomicAdd(&fill[d], 1);
        csrsrc[pos] = src16[i];
    }
    for (int i = tid; i < 4096; i += NTHREADS) {
        int k = i >> 5, c = i & 31;
        sW[c * 132 + k] = W1[i];
    }
    __syncthreads();

    // ---------------- Phase B: xw1 = dinv * (x @ W1), 4 nodes per warp ----------------
    {
        float* xs = hcat + warp * 528;      // per-warp scratch: 4 rows * 132
        const float* wrow = sW + lane * 132;
        for (int n0 = warp * 4; n0 < MNODES; n0 += NW * 4) {
            #pragma unroll
            for (int j = 0; j < 4; ++j) {
                float4 v = *(const float4*)(x + (size_t)(nbase + n0 + j) * 128 + lane * 4);
                *(float4*)(xs + j * 132 + lane * 4) = v;
            }
            __syncwarp();
            u64 a00 = 0, a01 = 0, a10 = 0, a11 = 0, a20 = 0, a21 = 0, a30 = 0, a31 = 0;
            #pragma unroll 4
            for (int k = 0; k < 128; k += 4) {
                ulonglong2 wv = *(const ulonglong2*)(wrow + k);
                ulonglong2 h0 = *(const ulonglong2*)(xs + k);
                ulonglong2 h1 = *(const ulonglong2*)(xs + 132 + k);
                ulonglong2 h2 = *(const ulonglong2*)(xs + 264 + k);
                ulonglong2 h3 = *(const ulonglong2*)(xs + 396 + k);
                a00 = fma2(h0.x, wv.x, a00); a01 = fma2(h0.y, wv.y, a01);
                a10 = fma2(h1.x, wv.x, a10); a11 = fma2(h1.y, wv.y, a11);
                a20 = fma2(h2.x, wv.x, a20); a21 = fma2(h2.y, wv.y, a21);
                a30 = fma2(h3.x, wv.x, a30); a31 = fma2(h3.y, wv.y, a31);
            }
            float2 r0 = u2f(add2(a00, a01)); xw[(n0 + 0) * 32 + lane] = dinv[n0 + 0] * (r0.x + r0.y);
            float2 r1 = u2f(add2(a10, a11)); xw[(n0 + 1) * 32 + lane] = dinv[n0 + 1] * (r1.x + r1.y);
            float2 r2 = u2f(add2(a20, a21)); xw[(n0 + 2) * 32 + lane] = dinv[n0 + 2] * (r2.x + r2.y);
            float2 r3 = u2f(add2(a30, a31)); xw[(n0 + 3) * 32 + lane] = dinv[n0 + 3] * (r3.x + r3.y);
            __syncwarp();
        }
    }
    __syncthreads();

    // ---------------- GCN aggregation layers 1-3 (F=32) ----------------
    const float* Bv[3] = { b1, b2, b3 };
    const float* Wv[2] = { W2, W3 };
    for (int layer = 0; layer < 3; ++layer) {
        int off = layer * 32;
        float2 blv = *(const float2*)(Bv[layer] + 2 * hl);
        // gather: 2 nodes per warp (half-warps), float2 per lane,
        // software-pipelined: 8 edges per iteration (4 packed idx words, 8 LDS.64 in flight)
        const float* xwh = xw + hl * 2;
        for (int p = warp; p < MNODES / 2; p += NW) {
            int node = p * 2 + half;
            int e0 = rowptr[node], e1 = rowptr[node + 1];
            u64 acc0 = *(const u64*)(xw + node * 32 + hl * 2);
            u64 acc1 = 0, acc2 = 0, acc3 = 0;
            int e = e0;
            if ((e & 1) && e < e1) {   // align to u32
                acc0 = add2(acc0, *(const u64*)(xwh + (int)csrsrc[e] * 32));
                ++e;
            }
            for (; e + 8 <= e1; e += 8) {
                unsigned pA = *(const unsigned*)(csrsrc + e);
                unsigned pB = *(const unsigned*)(csrsrc + e + 2);
                unsigned pC = *(const unsigned*)(csrsrc + e + 4);
                unsigned pD = *(const unsigned*)(csrsrc + e + 6);
                u64 v0 = *(const u64*)(xwh + (int)(pA & 0xffffu) * 32);
                u64 v1 = *(const u64*)(xwh + (int)(pA >> 16) * 32);
                u64 v2 = *(const u64*)(xwh + (int)(pB & 0xffffu) * 32);
                u64 v3 = *(const u64*)(xwh + (int)(pB >> 16) * 32);
                u64 v4 = *(const u64*)(xwh + (int)(pC & 0xffffu) * 32);
                u64 v5 = *(const u64*)(xwh + (int)(pC >> 16) * 32);
                u64 v6 = *(const u64*)(xwh + (int)(pD & 0xffffu) * 32);
                u64 v7 = *(const u64*)(xwh + (int)(pD >> 16) * 32);
                acc0 = add2(acc0, v0); acc1 = add2(acc1, v1);
                acc2 = add2(acc2, v2); acc3 = add2(acc3, v3);
                acc0 = add2(acc0, v4); acc1 = add2(acc1, v5);
                acc2 = add2(acc2, v6); acc3 = add2(acc3, v7);
            }
            for (; e + 2 <= e1; e += 2) {
                unsigned pr = *(const unsigned*)(csrsrc + e);
                acc0 = add2(acc0, *(const u64*)(xwh + (int)(pr & 0xffffu) * 32));
                acc1 = add2(acc1, *(const u64*)(xwh + (int)(pr >> 16) * 32));
            }
            if (e < e1)
                acc2 = add2(acc2, *(const u64*)(xwh + (int)csrsrc[e] * 32));
            float2 a = u2f(add2(add2(acc0, acc1), add2(acc2, acc3)));
            float dn = dinv[node];
            float* hp = hcat + node * 100 + off + hl * 2;
            hp[0] = fast_tanh(dn * a.x + blv.x);
            hp[1] = fast_tanh(dn * a.y + blv.y);
        }
        if (layer < 2) {
            for (int i = tid; i < 1024; i += NTHREADS) {
                int k = i >> 5, c = i & 31;
                sW[c * 36 + k] = Wv[layer][i];
            }
            __syncthreads();
            // xw_{l+1} = dinv * (h_l @ W), 4 nodes per warp
            const float* wrow = sW + lane * 36;
            for (int n0 = warp * 4; n0 < MNODES; n0 += NW * 4) {
                const float* hr0 = hcat + (n0 + 0) * 100 + off;
                const float* hr1 = hcat + (n0 + 1) * 100 + off;
                const float* hr2 = hcat + (n0 + 2) * 100 + off;
                const float* hr3 = hcat + (n0 + 3) * 100 + off;
                u64 a00 = 0, a01 = 0, a10 = 0, a11 = 0, a20 = 0, a21 = 0, a30 = 0, a31 = 0;
                #pragma unroll
                for (int k = 0; k < 32; k += 4) {
                    ulonglong2 wv = *(const ulonglong2*)(wrow + k);
                    ulonglong2 h0 = *(const ulonglong2*)(hr0 + k);
                    ulonglong2 h1 = *(const ulonglong2*)(hr1 + k);
                    ulonglong2 h2 = *(const ulonglong2*)(hr2 + k);
                    ulonglong2 h3 = *(const ulonglong2*)(hr3 + k);
                    a00 = fma2(h0.x, wv.x, a00); a01 = fma2(h0.y, wv.y, a01);
                    a10 = fma2(h1.x, wv.x, a10); a11 = fma2(h1.y, wv.y, a11);
                    a20 = fma2(h2.x, wv.x, a20); a21 = fma2(h2.y, wv.y, a21);
                    a30 = fma2(h3.x, wv.x, a30); a31 = fma2(h3.y, wv.y, a31);
                }
                float2 r0 = u2f(add2(a00, a01)); xw[(n0 + 0) * 32 + lane] = dinv[n0 + 0] * (r0.x + r0.y);
                float2 r1 = u2f(add2(a10, a11)); xw[(n0 + 1) * 32 + lane] = dinv[n0 + 1] * (r1.x + r1.y);
                float2 r2 = u2f(add2(a20, a21)); xw[(n0 + 2) * 32 + lane] = dinv[n0 + 2] * (r2.x + r2.y);
                float2 r3 = u2f(add2(a30, a31)); xw[(n0 + 3) * 32 + lane] = dinv[n0 + 3] * (r3.x + r3.y);
            }
            __syncthreads();
        } else {
            __syncthreads();
        }
    }

    // ---------------- Layer 4 (F=1) ----------------
    {
        float w4l = W4[lane];
        for (int n = warp; n < MNODES; n += NW) {
            float v = hcat[n * 100 + 64 + lane] * w4l;
            v = warp_sum(v);
            if (lane == 0) xw[n] = dinv[n] * v;   // xwd4[200]
        }
        __syncthreads();
        float b4v = b4[0];
        for (int n = tid; n < MNODES; n += NTHREADS) {
            float a0 = xw[n], a1 = 0.0f, a2 = 0.0f, a3 = 0.0f;
            int e = rowptr[n], e1 = rowptr[n + 1];
            for (; e + 4 <= e1; e += 4) {
                float v0 = xw[(int)csrsrc[e]];
                float v1 = xw[(int)csrsrc[e + 1]];
                float v2 = xw[(int)csrsrc[e + 2]];
                float v3 = xw[(int)csrsrc[e + 3]];
                a0 += v0; a1 += v1; a2 += v2; a3 += v3;
            }
            for (; e < e1; ++e) a1 += xw[(int)csrsrc[e]];
            float h4 = fast_tanh(dinv[n] * ((a0 + a2) + (a1 + a3)) + b4v);
            hcat[n * 100 + 96] = h4;
            sKey[n] = h4;
        }
        __syncthreads();
    }

    // ---------------- SortPool: stable top-30 by key desc (warp per node) ----------------
    for (int n = warp; n < MNODES; n += NW) {
        float ki = sKey[n];
        int cnt = 0;
        for (int j = lane; j < MNODES; j += 32) {
            float kj = sKey[j];
            cnt += (kj > ki) || (kj == ki && j < n);
        }
        cnt = __reduce_add_sync(0xffffffffu, cnt);
        if (lane == 0 && cnt < 30) sSel[cnt] = n;
    }
    for (int i = tid; i < 16 * 97; i += NTHREADS) sW[i] = convW1[i];
    for (int i = tid; i < 32 * 16 * 5; i += NTHREADS) sW[1552 + i] = convW2[i];
    __syncthreads();

    // ---------------- Conv1 (kernel 97, stride 97) -> [16][30], relu ----------------
    for (int it = warp; it < 480; it += NW) {
        int p = it / 16, oc = it % 16;
        int node = sSel[p];
        const float* hr = hcat + node * 100;
        const float* wr = sW + oc * 97;
        float v = hr[lane] * wr[lane] + hr[lane + 32] * wr[lane + 32]
                + hr[lane + 64] * wr[lane + 64];
        if (lane == 0) v += hr[96] * wr[96];
        v = warp_sum(v);
        if (lane == 0) sC1[oc * 30 + p] = fmaxf(v + convb1[oc], 0.0f);
    }
    __syncthreads();

    // ---------------- MaxPool1d(2,2) -> [16][15] ----------------
    for (int i = tid; i < 240; i += NTHREADS) {
        int oc = i / 15, t = i % 15;
        sPool[i] = fmaxf(sC1[oc * 30 + 2 * t], sC1[oc * 30 + 2 * t + 1]);
    }
    __syncthreads();

    // ---------------- Conv2 (16->32, k=5) -> [32][11], relu, flatten ----------------
    for (int it = tid; it < 352; it += NTHREADS) {
        int oc = it / 11, t = it % 11;
        float acc = convb2[oc];
        const float* w = sW + 1552 + oc * 80;
        #pragma unroll
        for (int ic = 0; ic < 16; ++ic) {
            #pragma unroll
            for (int k = 0; k < 5; ++k)
                acc += w[ic * 5 + k] * sPool[ic * 15 + t + k];
        }
        sFlat[oc * 11 + t] = fmaxf(acc, 0.0f);
    }
    __syncthreads();

    // ---------------- Linear 352->128 (split-K over 8 groups), relu ----------------
    {
        int grp = tid >> 7, t = tid & 127;
        float acc = 0.0f;
        int f0 = grp * 44, f1 = f0 + 44;
        for (int fi = f0; fi < f1; ++fi)
            acc += sFlat[fi] * linW1[fi * 128 + t];
        sW[grp * 128 + t] = acc;
    }
    __syncthreads();
    if (tid < 128) {
        float a = linb1[tid];
        #pragma unroll
        for (int grp = 0; grp < 8; ++grp) a += sW[grp * 128 + tid];
        sHlin[tid] = fmaxf(a, 0.0f);
    }
    __syncthreads();

    // ---------------- Linear 128->1, sigmoid ----------------
    if (warp == 0) {
        float acc = sHlin[lane] * linW2[lane] + sHlin[lane + 32] * linW2[lane + 32]
                  + sHlin[lane + 64] * linW2[lane + 64] + sHlin[lane + 96] * linW2[lane + 96];
        acc = warp_sum(acc);
        if (lane == 0) {
            float z = acc + linb2[0];
            out[g] = __fdividef(1.0f, 1.0f + __expf(-z));
        }
    }
}

extern "C" void kernel_launch(void* const* d_in, const int* in_sizes, int n_in,
                              void* d_out, int out_size) {
    const float* x      = (const float*)d_in[0];
    const int*   ei     = (const int*)  d_in[1];
    const float* W1     = (const float*)d_in[3];
    const float* b1     = (const float*)d_in[4];
    const float* W2     = (const float*)d_in[5];
    const float* b2     = (const float*)d_in[6];
    const float* W3     = (const float*)d_in[7];
    const float* b3     = (const float*)d_in[8];
    const float* W4     = (const float*)d_in[9];
    const float* b4     = (const float*)d_in[10];
    const float* convW1 = (const float*)d_in[11];
    const float* convb1 = (const float*)d_in[12];
    const float* convW2 = (const float*)d_in[13];
    const float* convb2 = (const float*)d_in[14];
    const float* linW1  = (const float*)d_in[15];
    const float* linb1  = (const float*)d_in[16];
    const float* linW2  = (const float*)d_in[17];
    const float* linb2  = (const float*)d_in[18];
    float* out = (float*)d_out;

    cudaFuncSetAttribute(dgcnn_kernel,
                         cudaFuncAttributeMaxDynamicSharedMemorySize, SMEM_BYTES);
    dgcnn_kernel<<<BGRAPHS, NTHREADS, SMEM_BYTES>>>(
        x, ei, W1, b1, W2, b2, W3, b3, W4, b4,
        convW1, convb1, convW2, convb2, linW1, linb1, linW2, linb2, out);
}

// round 10
// speedup vs baseline: 1.0071x; 1.0071x over previous
#include <cuda_runtime.h>
#include <math.h>

#define BGRAPHS 512
#define MNODES  200
#define EPG     6400
#define ETOT    3276800
#define NTHREADS 1024
#define NW 32
#define CSTRIDE 96          // fixed CSR bucket stride (max degree bound)

// ---- shared memory layout (float slots) ----
#define OFF_HCAT   0          // 200*100 = 20000 (also x@W1 per-warp scratch early)
#define OFF_XW     20000      // 200*32  = 6400   (holds dinv-scaled xw)
#define OFF_SW     26400      // 4224 weight/scratch staging (W1^T = 32*132)
#define OFF_DINV   30624      // 200
#define OFF_FILL   30824      // 200 ints (degree after scatter)
#define OFF_CSR    31024      // 200*96 u16 -> 9600 slots (values pre-scaled by 32)
#define OFF_KEY    40624      // 200
#define OFF_SEL    40824      // 32 ints
#define OFF_C1     40856      // 480
#define OFF_POOL   41336      // 240
#define OFF_FLAT   41576      // 352
#define OFF_HLIN   41928      // 128
#define SMEM_SLOTS 42056
#define SMEM_BYTES (SMEM_SLOTS * 4)

typedef unsigned long long u64;

__device__ __forceinline__ u64 fma2(u64 a, u64 b, u64 c) {
    u64 d; asm("fma.rn.f32x2 %0,%1,%2,%3;" : "=l"(d) : "l"(a), "l"(b), "l"(c)); return d;
}
__device__ __forceinline__ u64 add2(u64 a, u64 b) {
    u64 d; asm("add.rn.f32x2 %0,%1,%2;" : "=l"(d) : "l"(a), "l"(b)); return d;
}
__device__ __forceinline__ float2 u2f(u64 a) {
    float2 f; asm("mov.b64 {%0,%1},%2;" : "=f"(f.x), "=f"(f.y) : "l"(a)); return f;
}

__device__ __forceinline__ float warp_sum(float v) {
    #pragma unroll
    for (int o = 16; o > 0; o >>= 1) v += __shfl_down_sync(0xffffffffu, v, o);
    return v;
}

__device__ __forceinline__ float fast_tanh(float x) {
    float xc = fminf(fmaxf(x, -15.0f), 15.0f);
    float t = __expf(2.0f * xc);
    return __fdividef(t - 1.0f, t + 1.0f);
}

__global__ __launch_bounds__(NTHREADS, 1)
void dgcnn_kernel(
    const float* __restrict__ x, const int* __restrict__ ei,
    const float* __restrict__ W1, const float* __restrict__ b1,
    const float* __restrict__ W2, const float* __restrict__ b2,
    const float* __restrict__ W3, const float* __restrict__ b3,
    const float* __restrict__ W4, const float* __restrict__ b4,
    const float* __restrict__ convW1, const float* __restrict__ convb1,
    const float* __restrict__ convW2, const float* __restrict__ convb2,
    const float* __restrict__ linW1, const float* __restrict__ linb1,
    const float* __restrict__ linW2, const float* __restrict__ linb2,
    float* __restrict__ out)
{
    extern __shared__ float smem[];
    float* hcat   = smem + OFF_HCAT;    // [200][100]
    float* xw     = smem + OFF_XW;      // [200][32] (dinv-scaled)
    float* sW     = smem + OFF_SW;      // transposed weight staging / scratch
    float* dinv   = smem + OFF_DINV;
    int*   fill   = (int*)(smem + OFF_FILL);
    unsigned short* csrsrc = (unsigned short*)(smem + OFF_CSR);  // [200][96], pre-scaled x32
    float* sKey   = smem + OFF_KEY;
    int*   sSel   = (int*)(smem + OFF_SEL);
    float* sC1    = smem + OFF_C1;
    float* sPool  = smem + OFF_POOL;
    float* sFlat  = smem + OFF_FLAT;
    float* sHlin  = smem + OFF_HLIN;

    const int g    = blockIdx.x;
    const int tid  = threadIdx.x;
    const int lane = tid & 31;
    const int warp = tid >> 5;
    const int half = lane >> 4;      // 0/1: which node of the pair (gather)
    const int hl   = lane & 15;      // feature-pair index within node
    const int nbase = g * MNODES;
    const long ebase = (long)g * EPG;
    const int* srcg = ei + ebase;
    const int* dstg = ei + (long)ETOT + ebase;

    // ---------------- Phase A: single-pass bucket CSR (no degree pass, no staging) ----------------
    for (int i = tid; i < MNODES; i += NTHREADS) fill[i] = 0;
    __syncthreads();
    for (int i = tid; i < EPG / 4; i += NTHREADS) {
        int4 s4 = ((const int4*)srcg)[i];
        int4 d4 = ((const int4*)dstg)[i];
        int s, d, pos;
        s = s4.x - nbase; d = d4.x - nbase;
        pos = atomicAdd(&fill[d], 1); csrsrc[d * CSTRIDE + pos] = (unsigned short)(s << 5);
        s = s4.y - nbase; d = d4.y - nbase;
        pos = atomicAdd(&fill[d], 1); csrsrc[d * CSTRIDE + pos] = (unsigned short)(s << 5);
        s = s4.z - nbase; d = d4.z - nbase;
        pos = atomicAdd(&fill[d], 1); csrsrc[d * CSTRIDE + pos] = (unsigned short)(s << 5);
        s = s4.w - nbase; d = d4.w - nbase;
        pos = atomicAdd(&fill[d], 1); csrsrc[d * CSTRIDE + pos] = (unsigned short)(s << 5);
    }
    // stage W1^T concurrently: sW[c*132 + k] = W1[k*32 + c]
    for (int i = tid; i < 4096; i += NTHREADS) {
        int k = i >> 5, c = i & 31;
        sW[c * 132 + k] = W1[i];
    }
    __syncthreads();
    for (int i = tid; i < MNODES; i += NTHREADS)
        dinv[i] = rsqrtf((float)fill[i] + 1.0f);
    __syncthreads();

    // ---------------- Phase B: xw1 = dinv * (x @ W1), 4 nodes per warp ----------------
    {
        float* xs = hcat + warp * 528;      // per-warp scratch: 4 rows * 132
        const float* wrow = sW + lane * 132;
        for (int n0 = warp * 4; n0 < MNODES; n0 += NW * 4) {
            #pragma unroll
            for (int j = 0; j < 4; ++j) {
                float4 v = *(const float4*)(x + (size_t)(nbase + n0 + j) * 128 + lane * 4);
                *(float4*)(xs + j * 132 + lane * 4) = v;
            }
            __syncwarp();
            u64 a00 = 0, a01 = 0, a10 = 0, a11 = 0, a20 = 0, a21 = 0, a30 = 0, a31 = 0;
            #pragma unroll 4
            for (int k = 0; k < 128; k += 4) {
                ulonglong2 wv = *(const ulonglong2*)(wrow + k);
                ulonglong2 h0 = *(const ulonglong2*)(xs + k);
                ulonglong2 h1 = *(const ulonglong2*)(xs + 132 + k);
                ulonglong2 h2 = *(const ulonglong2*)(xs + 264 + k);
                ulonglong2 h3 = *(const ulonglong2*)(xs + 396 + k);
                a00 = fma2(h0.x, wv.x, a00); a01 = fma2(h0.y, wv.y, a01);
                a10 = fma2(h1.x, wv.x, a10); a11 = fma2(h1.y, wv.y, a11);
                a20 = fma2(h2.x, wv.x, a20); a21 = fma2(h2.y, wv.y, a21);
                a30 = fma2(h3.x, wv.x, a30); a31 = fma2(h3.y, wv.y, a31);
            }
            float2 r0 = u2f(add2(a00, a01)); xw[(n0 + 0) * 32 + lane] = dinv[n0 + 0] * (r0.x + r0.y);
            float2 r1 = u2f(add2(a10, a11)); xw[(n0 + 1) * 32 + lane] = dinv[n0 + 1] * (r1.x + r1.y);
            float2 r2 = u2f(add2(a20, a21)); xw[(n0 + 2) * 32 + lane] = dinv[n0 + 2] * (r2.x + r2.y);
            float2 r3 = u2f(add2(a30, a31)); xw[(n0 + 3) * 32 + lane] = dinv[n0 + 3] * (r3.x + r3.y);
            __syncwarp();
        }
    }
    __syncthreads();

    // ---------------- GCN aggregation layers 1-3 (F=32) ----------------
    const float* Bv[3] = { b1, b2, b3 };
    const float* Wv[2] = { W2, W3 };
    for (int layer = 0; layer < 3; ++layer) {
        int off = layer * 32;
        float2 blv = *(const float2*)(Bv[layer] + 2 * hl);
        // gather: 2 nodes per warp (half-warps), float2 per lane, packed pre-scaled idx
        const float* xwh = xw + hl * 2;
        for (int p = warp; p < MNODES / 2; p += NW) {
            int node = p * 2 + half;
            int cnt = fill[node];
            const unsigned short* cp = csrsrc + node * CSTRIDE;   // even base -> u32-aligned
            u64 acc0 = *(const u64*)(xw + node * 32 + hl * 2);
            u64 acc1 = 0;
            int e = 0;
            for (; e + 2 <= cnt; e += 2) {
                unsigned pr = *(const unsigned*)(cp + e);
                acc0 = add2(acc0, *(const u64*)(xwh + (pr & 0xffffu)));
                acc1 = add2(acc1, *(const u64*)(xwh + (pr >> 16)));
            }
            if (e < cnt)
                acc1 = add2(acc1, *(const u64*)(xwh + (unsigned)cp[e]));
            float2 a = u2f(add2(acc0, acc1));
            float dn = dinv[node];
            float* hp = hcat + node * 100 + off + hl * 2;
            hp[0] = fast_tanh(dn * a.x + blv.x);
            hp[1] = fast_tanh(dn * a.y + blv.y);
        }
        if (layer < 2) {
            for (int i = tid; i < 1024; i += NTHREADS) {
                int k = i >> 5, c = i & 31;
                sW[c * 36 + k] = Wv[layer][i];
            }
            __syncthreads();
            // xw_{l+1} = dinv * (h_l @ W), 4 nodes per warp
            const float* wrow = sW + lane * 36;
            for (int n0 = warp * 4; n0 < MNODES; n0 += NW * 4) {
                const float* hr0 = hcat + (n0 + 0) * 100 + off;
                const float* hr1 = hcat + (n0 + 1) * 100 + off;
                const float* hr2 = hcat + (n0 + 2) * 100 + off;
                const float* hr3 = hcat + (n0 + 3) * 100 + off;
                u64 a00 = 0, a01 = 0, a10 = 0, a11 = 0, a20 = 0, a21 = 0, a30 = 0, a31 = 0;
                #pragma unroll
                for (int k = 0; k < 32; k += 4) {
                    ulonglong2 wv = *(const ulonglong2*)(wrow + k);
                    ulonglong2 h0 = *(const ulonglong2*)(hr0 + k);
                    ulonglong2 h1 = *(const ulonglong2*)(hr1 + k);
                    ulonglong2 h2 = *(const ulonglong2*)(hr2 + k);
                    ulonglong2 h3 = *(const ulonglong2*)(hr3 + k);
                    a00 = fma2(h0.x, wv.x, a00); a01 = fma2(h0.y, wv.y, a01);
                    a10 = fma2(h1.x, wv.x, a10); a11 = fma2(h1.y, wv.y, a11);
                    a20 = fma2(h2.x, wv.x, a20); a21 = fma2(h2.y, wv.y, a21);
                    a30 = fma2(h3.x, wv.x, a30); a31 = fma2(h3.y, wv.y, a31);
                }
                float2 r0 = u2f(add2(a00, a01)); xw[(n0 + 0) * 32 + lane] = dinv[n0 + 0] * (r0.x + r0.y);
                float2 r1 = u2f(add2(a10, a11)); xw[(n0 + 1) * 32 + lane] = dinv[n0 + 1] * (r1.x + r1.y);
                float2 r2 = u2f(add2(a20, a21)); xw[(n0 + 2) * 32 + lane] = dinv[n0 + 2] * (r2.x + r2.y);
                float2 r3 = u2f(add2(a30, a31)); xw[(n0 + 3) * 32 + lane] = dinv[n0 + 3] * (r3.x + r3.y);
            }
            __syncthreads();
        } else {
            __syncthreads();
        }
    }

    // ---------------- Layer 4 (F=1) ----------------
    {
        float w4l = W4[lane];
        for (int n = warp; n < MNODES; n += NW) {
            float v = hcat[n * 100 + 64 + lane] * w4l;
            v = warp_sum(v);
            if (lane == 0) xw[n] = dinv[n] * v;   // xwd4[200]
        }
        __syncthreads();
        float b4v = b4[0];
        for (int n = tid; n < MNODES; n += NTHREADS) {
            const unsigned short* cp = csrsrc + n * CSTRIDE;
            int cnt = fill[n];
            float a0 = xw[n], a1 = 0.0f, a2 = 0.0f, a3 = 0.0f;
            int e = 0;
            for (; e + 4 <= cnt; e += 4) {
                float v0 = xw[cp[e]     >> 5];
                float v1 = xw[cp[e + 1] >> 5];
                float v2 = xw[cp[e + 2] >> 5];
                float v3 = xw[cp[e + 3] >> 5];
                a0 += v0; a1 += v1; a2 += v2; a3 += v3;
            }
            for (; e < cnt; ++e) a1 += xw[cp[e] >> 5];
            float h4 = fast_tanh(dinv[n] * ((a0 + a2) + (a1 + a3)) + b4v);
            hcat[n * 100 + 96] = h4;
            sKey[n] = h4;
        }
        __syncthreads();
    }

    // ---------------- SortPool: stable top-30 by key desc (warp per node) ----------------
    for (int n = warp; n < MNODES; n += NW) {
        float ki = sKey[n];
        int cnt = 0;
        for (int j = lane; j < MNODES; j += 32) {
            float kj = sKey[j];
            cnt += (kj > ki) || (kj == ki && j < n);
        }
        cnt = __reduce_add_sync(0xffffffffu, cnt);
        if (lane == 0 && cnt < 30) sSel[cnt] = n;
    }
    for (int i = tid; i < 16 * 97; i += NTHREADS) sW[i] = convW1[i];
    for (int i = tid; i < 32 * 16 * 5; i += NTHREADS) sW[1552 + i] = convW2[i];
    __syncthreads();

    // ---------------- Conv1 (kernel 97, stride 97) -> [16][30], relu ----------------
    for (int it = warp; it < 480; it += NW) {
        int p = it / 16, oc = it % 16;
        int node = sSel[p];
        const float* hr = hcat + node * 100;
        const float* wr = sW + oc * 97;
        float v = hr[lane] * wr[lane] + hr[lane + 32] * wr[lane + 32]
                + hr[lane + 64] * wr[lane + 64];
        if (lane == 0) v += hr[96] * wr[96];
        v = warp_sum(v);
        if (lane == 0) sC1[oc * 30 + p] = fmaxf(v + convb1[oc], 0.0f);
    }
    __syncthreads();

    // ---------------- MaxPool1d(2,2) -> [16][15] ----------------
    for (int i = tid; i < 240; i += NTHREADS) {
        int oc = i / 15, t = i % 15;
        sPool[i] = fmaxf(sC1[oc * 30 + 2 * t], sC1[oc * 30 + 2 * t + 1]);
    }
    __syncthreads();

    // ---------------- Conv2 (16->32, k=5) -> [32][11], relu, flatten ----------------
    for (int it = tid; it < 352; it += NTHREADS) {
        int oc = it / 11, t = it % 11;
        float acc = convb2[oc];
        const float* w = sW + 1552 + oc * 80;
        #pragma unroll
        for (int ic = 0; ic < 16; ++ic) {
            #pragma unroll
            for (int k = 0; k < 5; ++k)
                acc += w[ic * 5 + k] * sPool[ic * 15 + t + k];
        }
        sFlat[oc * 11 + t] = fmaxf(acc, 0.0f);
    }
    __syncthreads();

    // ---------------- Linear 352->128 (split-K over 8 groups), relu ----------------
    {
        int grp = tid >> 7, t = tid & 127;
        float acc = 0.0f;
        int f0 = grp * 44, f1 = f0 + 44;
        for (int fi = f0; fi < f1; ++fi)
            acc += sFlat[fi] * linW1[fi * 128 + t];
        sW[grp * 128 + t] = acc;
    }
    __syncthreads();
    if (tid < 128) {
        float a = linb1[tid];
        #pragma unroll
        for (int grp = 0; grp < 8; ++grp) a += sW[grp * 128 + tid];
        sHlin[tid] = fmaxf(a, 0.0f);
    }
    __syncthreads();

    // ---------------- Linear 128->1, sigmoid ----------------
    if (warp == 0) {
        float acc = sHlin[lane] * linW2[lane] + sHlin[lane + 32] * linW2[lane + 32]
                  + sHlin[lane + 64] * linW2[lane + 64] + sHlin[lane + 96] * linW2[lane + 96];
        acc = warp_sum(acc);
        if (lane == 0) {
            float z = acc + linb2[0];
            out[g] = __fdividef(1.0f, 1.0f + __expf(-z));
        }
    }
}

extern "C" void kernel_launch(void* const* d_in, const int* in_sizes, int n_in,
                              void* d_out, int out_size) {
    const float* x      = (const float*)d_in[0];
    const int*   ei     = (const int*)  d_in[1];
    const float* W1     = (const float*)d_in[3];
    const float* b1     = (const float*)d_in[4];
    const float* W2     = (const float*)d_in[5];
    const float* b2     = (const float*)d_in[6];
    const float* W3     = (const float*)d_in[7];
    const float* b3     = (const float*)d_in[8];
    const float* W4     = (const float*)d_in[9];
    const float* b4     = (const float*)d_in[10];
    const float* convW1 = (const float*)d_in[11];
    const float* convb1 = (const float*)d_in[12];
    const float* convW2 = (const float*)d_in[13];
    const float* convb2 = (const float*)d_in[14];
    const float* linW1  = (const float*)d_in[15];
    const float* linb1  = (const float*)d_in[16];
    const float* linW2  = (const float*)d_in[17];
    const float* linb2  = (const float*)d_in[18];
    float* out = (float*)d_out;

    cudaFuncSetAttribute(dgcnn_kernel,
                         cudaFuncAttributeMaxDynamicSharedMemorySize, SMEM_BYTES);
    dgcnn_kernel<<<BGRAPHS, NTHREADS, SMEM_BYTES>>>(
        x, ei, W1, b1, W2, b2, W3, b3, W4, b4,
        convW1, convb1, convW2, convb2, linW1, linb1, linW2, linb2, out);
}

// round 12
// speedup vs baseline: 1.0097x; 1.0025x over previous
#include <cuda_runtime.h>
#include <math.h>

#define BGRAPHS 512
#define MNODES  200
#define EPG     6400
#define ETOT    3276800
#define NTHREADS 1024
#define NW 32
#define CSTRIDE 96          // fixed CSR bucket stride (max degree bound)

// ---- shared memory layout (float slots) ----
#define OFF_HCAT   0          // 200*100 = 20000 (also x@W1 per-warp scratch early)
#define OFF_XW     20000      // 200*32  = 6400   (holds dinv-scaled xw)
#define OFF_SW     26400      // 4224 weight/scratch staging (W1^T = 32*132)
#define OFF_DINV   30624      // 200
#define OFF_FILL   30824      // 200 ints (degree after scatter)
#define OFF_CSR    31024      // 200*96 u16 -> 9600 slots (values pre-scaled by 32)
#define OFF_KEY    40624      // 200
#define OFF_SEL    40824      // 32 ints
#define OFF_C1     40856      // 480
#define OFF_POOL   41336      // 240
#define OFF_FLAT   41576      // 352
#define OFF_HLIN   41928      // 128
#define SMEM_SLOTS 42056
#define SMEM_BYTES (SMEM_SLOTS * 4)

typedef unsigned long long u64;

__device__ __forceinline__ u64 fma2(u64 a, u64 b, u64 c) {
    u64 d; asm("fma.rn.f32x2 %0,%1,%2,%3;" : "=l"(d) : "l"(a), "l"(b), "l"(c)); return d;
}
__device__ __forceinline__ u64 add2(u64 a, u64 b) {
    u64 d; asm("add.rn.f32x2 %0,%1,%2;" : "=l"(d) : "l"(a), "l"(b)); return d;
}
__device__ __forceinline__ float2 u2f(u64 a) {
    float2 f; asm("mov.b64 {%0,%1},%2;" : "=f"(f.x), "=f"(f.y) : "l"(a)); return f;
}

__device__ __forceinline__ float warp_sum(float v) {
    #pragma unroll
    for (int o = 16; o > 0; o >>= 1) v += __shfl_down_sync(0xffffffffu, v, o);
    return v;
}

__device__ __forceinline__ float fast_tanh(float x) {
    float xc = fminf(fmaxf(x, -15.0f), 15.0f);
    float t = __expf(2.0f * xc);
    return __fdividef(t - 1.0f, t + 1.0f);
}

__global__ __launch_bounds__(NTHREADS, 1)
void dgcnn_kernel(
    const float* __restrict__ x, const int* __restrict__ ei,
    const float* __restrict__ W1, const float* __restrict__ b1,
    const float* __restrict__ W2, const float* __restrict__ b2,
    const float* __restrict__ W3, const float* __restrict__ b3,
    const float* __restrict__ W4, const float* __restrict__ b4,
    const float* __restrict__ convW1, const float* __restrict__ convb1,
    const float* __restrict__ convW2, const float* __restrict__ convb2,
    const float* __restrict__ linW1, const float* __restrict__ linb1,
    const float* __restrict__ linW2, const float* __restrict__ linb2,
    float* __restrict__ out)
{
    extern __shared__ float smem[];
    float* hcat   = smem + OFF_HCAT;    // [200][100]
    float* xw     = smem + OFF_XW;      // [200][32] (dinv-scaled)
    float* sW     = smem + OFF_SW;      // transposed weight staging / scratch
    float* dinv   = smem + OFF_DINV;
    int*   fill   = (int*)(smem + OFF_FILL);
    unsigned short* csrsrc = (unsigned short*)(smem + OFF_CSR);  // [200][96], pre-scaled x32
    float* sKey   = smem + OFF_KEY;
    int*   sSel   = (int*)(smem + OFF_SEL);
    float* sC1    = smem + OFF_C1;
    float* sPool  = smem + OFF_POOL;
    float* sFlat  = smem + OFF_FLAT;
    float* sHlin  = smem + OFF_HLIN;

    const int g    = blockIdx.x;
    const int tid  = threadIdx.x;
    const int lane = tid & 31;
    const int warp = tid >> 5;
    const int half = lane >> 4;      // 0/1: which node of the pair (gather)
    const int hl   = lane & 15;      // feature-pair index within node
    const int nbase = g * MNODES;
    const long ebase = (long)g * EPG;
    const int* srcg = ei + ebase;
    const int* dstg = ei + (long)ETOT + ebase;

    // ---------------- Phase A: single-pass bucket CSR (no degree pass, no staging) ----------------
    for (int i = tid; i < MNODES; i += NTHREADS) fill[i] = 0;
    __syncthreads();
    for (int i = tid; i < EPG / 4; i += NTHREADS) {
        int4 s4 = ((const int4*)srcg)[i];
        int4 d4 = ((const int4*)dstg)[i];
        int s, d, pos;
        s = s4.x - nbase; d = d4.x - nbase;
        pos = atomicAdd(&fill[d], 1); csrsrc[d * CSTRIDE + pos] = (unsigned short)(s << 5);
        s = s4.y - nbase; d = d4.y - nbase;
        pos = atomicAdd(&fill[d], 1); csrsrc[d * CSTRIDE + pos] = (unsigned short)(s << 5);
        s = s4.z - nbase; d = d4.z - nbase;
        pos = atomicAdd(&fill[d], 1); csrsrc[d * CSTRIDE + pos] = (unsigned short)(s << 5);
        s = s4.w - nbase; d = d4.w - nbase;
        pos = atomicAdd(&fill[d], 1); csrsrc[d * CSTRIDE + pos] = (unsigned short)(s << 5);
    }
    // stage W1^T concurrently: sW[c*132 + k] = W1[k*32 + c]
    for (int i = tid; i < 4096; i += NTHREADS) {
        int k = i >> 5, c = i & 31;
        sW[c * 132 + k] = W1[i];
    }
    __syncthreads();
    for (int i = tid; i < MNODES; i += NTHREADS)
        dinv[i] = rsqrtf((float)fill[i] + 1.0f);
    __syncthreads();

    // ---------------- Phase B: xw1 = dinv * (x @ W1), 4 nodes per warp ----------------
    {
        float* xs = hcat + warp * 528;      // per-warp scratch: 4 rows * 132
        const float* wrow = sW + lane * 132;
        for (int n0 = warp * 4; n0 < MNODES; n0 += NW * 4) {
            #pragma unroll
            for (int j = 0; j < 4; ++j) {
                float4 v = *(const float4*)(x + (size_t)(nbase + n0 + j) * 128 + lane * 4);
                *(float4*)(xs + j * 132 + lane * 4) = v;
            }
            __syncwarp();
            u64 a00 = 0, a01 = 0, a10 = 0, a11 = 0, a20 = 0, a21 = 0, a30 = 0, a31 = 0;
            #pragma unroll 4
            for (int k = 0; k < 128; k += 4) {
                ulonglong2 wv = *(const ulonglong2*)(wrow + k);
                ulonglong2 h0 = *(const ulonglong2*)(xs + k);
                ulonglong2 h1 = *(const ulonglong2*)(xs + 132 + k);
                ulonglong2 h2 = *(const ulonglong2*)(xs + 264 + k);
                ulonglong2 h3 = *(const ulonglong2*)(xs + 396 + k);
                a00 = fma2(h0.x, wv.x, a00); a01 = fma2(h0.y, wv.y, a01);
                a10 = fma2(h1.x, wv.x, a10); a11 = fma2(h1.y, wv.y, a11);
                a20 = fma2(h2.x, wv.x, a20); a21 = fma2(h2.y, wv.y, a21);
                a30 = fma2(h3.x, wv.x, a30); a31 = fma2(h3.y, wv.y, a31);
            }
            float2 r0 = u2f(add2(a00, a01)); xw[(n0 + 0) * 32 + lane] = dinv[n0 + 0] * (r0.x + r0.y);
            float2 r1 = u2f(add2(a10, a11)); xw[(n0 + 1) * 32 + lane] = dinv[n0 + 1] * (r1.x + r1.y);
            float2 r2 = u2f(add2(a20, a21)); xw[(n0 + 2) * 32 + lane] = dinv[n0 + 2] * (r2.x + r2.y);
            float2 r3 = u2f(add2(a30, a31)); xw[(n0 + 3) * 32 + lane] = dinv[n0 + 3] * (r3.x + r3.y);
            __syncwarp();
        }
    }
    __syncthreads();

    // ---------------- GCN aggregation layers 1-3 (F=32) ----------------
    const float* Bv[3] = { b1, b2, b3 };
    const float* Wv[2] = { W2, W3 };
    for (int layer = 0; layer < 3; ++layer) {
        int off = layer * 32;
        float2 blv = *(const float2*)(Bv[layer] + 2 * hl);
        // gather: 2 nodes per warp (half-warps), float2 per lane, packed pre-scaled idx
        const float* xwh = xw + hl * 2;
        for (int p = warp; p < MNODES / 2; p += NW) {
            int node = p * 2 + half;
            int cnt = fill[node];
            const unsigned short* cp = csrsrc + node * CSTRIDE;   // even base -> u32-aligned
            u64 acc0 = *(const u64*)(xw + node * 32 + hl * 2);
            u64 acc1 = 0;
            int e = 0;
            for (; e + 2 <= cnt; e += 2) {
                unsigned pr = *(const unsigned*)(cp + e);
                acc0 = add2(acc0, *(const u64*)(xwh + (pr & 0xffffu)));
                acc1 = add2(acc1, *(const u64*)(xwh + (pr >> 16)));
            }
            if (e < cnt)
                acc1 = add2(acc1, *(const u64*)(xwh + (unsigned)cp[e]));
            float2 a = u2f(add2(acc0, acc1));
            float dn = dinv[node];
            float* hp = hcat + node * 100 + off + hl * 2;
            hp[0] = fast_tanh(dn * a.x + blv.x);
            hp[1] = fast_tanh(dn * a.y + blv.y);
        }
        if (layer < 2) {
            for (int i = tid; i < 1024; i += NTHREADS) {
                int k = i >> 5, c = i & 31;
                sW[c * 36 + k] = Wv[layer][i];
            }
            __syncthreads();
            // xw_{l+1} = dinv * (h_l @ W), 4 nodes per warp
            const float* wrow = sW + lane * 36;
            for (int n0 = warp * 4; n0 < MNODES; n0 += NW * 4) {
                const float* hr0 = hcat + (n0 + 0) * 100 + off;
                const float* hr1 = hcat + (n0 + 1) * 100 + off;
                const float* hr2 = hcat + (n0 + 2) * 100 + off;
                const float* hr3 = hcat + (n0 + 3) * 100 + off;
                u64 a00 = 0, a01 = 0, a10 = 0, a11 = 0, a20 = 0, a21 = 0, a30 = 0, a31 = 0;
                #pragma unroll
                for (int k = 0; k < 32; k += 4) {
                    ulonglong2 wv = *(const ulonglong2*)(wrow + k);
                    ulonglong2 h0 = *(const ulonglong2*)(hr0 + k);
                    ulonglong2 h1 = *(const ulonglong2*)(hr1 + k);
                    ulonglong2 h2 = *(const ulonglong2*)(hr2 + k);
                    ulonglong2 h3 = *(const ulonglong2*)(hr3 + k);
                    a00 = fma2(h0.x, wv.x, a00); a01 = fma2(h0.y, wv.y, a01);
                    a10 = fma2(h1.x, wv.x, a10); a11 = fma2(h1.y, wv.y, a11);
                    a20 = fma2(h2.x, wv.x, a20); a21 = fma2(h2.y, wv.y, a21);
                    a30 = fma2(h3.x, wv.x, a30); a31 = fma2(h3.y, wv.y, a31);
                }
                float2 r0 = u2f(add2(a00, a01)); xw[(n0 + 0) * 32 + lane] = dinv[n0 + 0] * (r0.x + r0.y);
                float2 r1 = u2f(add2(a10, a11)); xw[(n0 + 1) * 32 + lane] = dinv[n0 + 1] * (r1.x + r1.y);
                float2 r2 = u2f(add2(a20, a21)); xw[(n0 + 2) * 32 + lane] = dinv[n0 + 2] * (r2.x + r2.y);
                float2 r3 = u2f(add2(a30, a31)); xw[(n0 + 3) * 32 + lane] = dinv[n0 + 3] * (r3.x + r3.y);
            }
            __syncthreads();
        } else {
            __syncthreads();
        }
    }

    // ---------------- Layer 4 (F=1) ----------------
    {
        float w4l = W4[lane];
        for (int n = warp; n < MNODES; n += NW) {
            float v = hcat[n * 100 + 64 + lane] * w4l;
            v = warp_sum(v);
            if (lane == 0) xw[n] = dinv[n] * v;   // xwd4[200]
        }
        __syncthreads();
        float b4v = b4[0];
        for (int n = tid; n < MNODES; n += NTHREADS) {
            const unsigned short* cp = csrsrc + n * CSTRIDE;
            int cnt = fill[n];
            float a0 = xw[n], a1 = 0.0f, a2 = 0.0f, a3 = 0.0f;
            int e = 0;
            for (; e + 4 <= cnt; e += 4) {
                float v0 = xw[cp[e]     >> 5];
                float v1 = xw[cp[e + 1] >> 5];
                float v2 = xw[cp[e + 2] >> 5];
                float v3 = xw[cp[e + 3] >> 5];
                a0 += v0; a1 += v1; a2 += v2; a3 += v3;
            }
            for (; e < cnt; ++e) a1 += xw[cp[e] >> 5];
            float h4 = fast_tanh(dinv[n] * ((a0 + a2) + (a1 + a3)) + b4v);
            hcat[n * 100 + 96] = h4;
            sKey[n] = h4;
        }
        __syncthreads();
    }

    // ---------------- SortPool: stable top-30 by key desc (warp per node) ----------------
    for (int n = warp; n < MNODES; n += NW) {
        float ki = sKey[n];
        int cnt = 0;
        for (int j = lane; j < MNODES; j += 32) {
            float kj = sKey[j];
            cnt += (kj > ki) || (kj == ki && j < n);
        }
        cnt = __reduce_add_sync(0xffffffffu, cnt);
        if (lane == 0 && cnt < 30) sSel[cnt] = n;
    }
    for (int i = tid; i < 16 * 97; i += NTHREADS) sW[i] = convW1[i];
    for (int i = tid; i < 32 * 16 * 5; i += NTHREADS) sW[1552 + i] = convW2[i];
    __syncthreads();

    // ---------------- Conv1 (kernel 97, stride 97) -> [16][30], relu ----------------
    for (int it = warp; it < 480; it += NW) {
        int p = it / 16, oc = it % 16;
        int node = sSel[p];
        const float* hr = hcat + node * 100;
        const float* wr = sW + oc * 97;
        float v = hr[lane] * wr[lane] + hr[lane + 32] * wr[lane + 32]
                + hr[lane + 64] * wr[lane + 64];
        if (lane == 0) v += hr[96] * wr[96];
        v = warp_sum(v);
        if (lane == 0) sC1[oc * 30 + p] = fmaxf(v + convb1[oc], 0.0f);
    }
    __syncthreads();

    // ---------------- MaxPool1d(2,2) -> [16][15] ----------------
    for (int i = tid; i < 240; i += NTHREADS) {
        int oc = i / 15, t = i % 15;
        sPool[i] = fmaxf(sC1[oc * 30 + 2 * t], sC1[oc * 30 + 2 * t + 1]);
    }
    __syncthreads();

    // ---------------- Conv2 (16->32, k=5) -> [32][11], relu, flatten ----------------
    for (int it = tid; it < 352; it += NTHREADS) {
        int oc = it / 11, t = it % 11;
        float acc = convb2[oc];
        const float* w = sW + 1552 + oc * 80;
        #pragma unroll
        for (int ic = 0; ic < 16; ++ic) {
            #pragma unroll
            for (int k = 0; k < 5; ++k)
                acc += w[ic * 5 + k] * sPool[ic * 15 + t + k];
        }
        sFlat[oc * 11 + t] = fmaxf(acc, 0.0f);
    }
    __syncthreads();

    // ---------------- Linear 352->128 (split-K over 8 groups), relu ----------------
    {
        int grp = tid >> 7, t = tid & 127;
        float acc = 0.0f;
        int f0 = grp * 44, f1 = f0 + 44;
        for (int fi = f0; fi < f1; ++fi)
            acc += sFlat[fi] * linW1[fi * 128 + t];
        sW[grp * 128 + t] = acc;
    }
    __syncthreads();
    if (tid < 128) {
        float a = linb1[tid];
        #pragma unroll
        for (int grp = 0; grp < 8; ++grp) a += sW[grp * 128 + tid];
        sHlin[tid] = fmaxf(a, 0.0f);
    }
    __syncthreads();

    // ---------------- Linear 128->1, sigmoid ----------------
    if (warp == 0) {
        float acc = sHlin[lane] * linW2[lane] + sHlin[lane + 32] * linW2[lane + 32]
                  + sHlin[lane + 64] * linW2[lane + 64] + sHlin[lane + 96] * linW2[lane + 96];
        acc = warp_sum(acc);
        if (lane == 0) {
            float z = acc + linb2[0];
            out[g] = __fdividef(1.0f, 1.0f + __expf(-z));
        }
    }
}

extern "C" void kernel_launch(void* const* d_in, const int* in_sizes, int n_in,
                              void* d_out, int out_size) {
    const float* x      = (const float*)d_in[0];
    const int*   ei     = (const int*)  d_in[1];
    const float* W1     = (const float*)d_in[3];
    const float* b1     = (const float*)d_in[4];
    const float* W2     = (const float*)d_in[5];
    const float* b2     = (const float*)d_in[6];
    const float* W3     = (const float*)d_in[7];
    const float* b3     = (const float*)d_in[8];
    const float* W4     = (const float*)d_in[9];
    const float* b4     = (const float*)d_in[10];
    const float* convW1 = (const float*)d_in[11];
    const float* convb1 = (const float*)d_in[12];
    const float* convW2 = (const float*)d_in[13];
    const float* convb2 = (const float*)d_in[14];
    const float* linW1  = (const float*)d_in[15];
    const float* linb1  = (const float*)d_in[16];
    const float* linW2  = (const float*)d_in[17];
    const float* linb2  = (const float*)d_in[18];
    float* out = (float*)d_out;

    cudaFuncSetAttribute(dgcnn_kernel,
                         cudaFuncAttributeMaxDynamicSharedMemorySize, SMEM_BYTES);
    dgcnn_kernel<<<BGRAPHS, NTHREADS, SMEM_BYTES>>>(
        x, ei, W1, b1, W2, b2, W3, b3, W4, b4,
        convW1, convb1, convW2, convb2, linW1, linb1, linW2, linb2, out);
}

// round 13
// speedup vs baseline: 1.0278x; 1.0180x over previous
#include <cuda_runtime.h>
#include <math.h>

#define BGRAPHS 512
#define MNODES  200
#define EPG     6400
#define ETOT    3276800
#define NTHREADS 1024
#define NW 32
#define GEMM_WARPS 24           // warps 0-23: x@W1 crew
// warps 24-31: CSR crew (256 threads)

// ---- shared memory layout (float slots) ----
#define OFF_HCAT   0          // 200*100 = 20000 (also x@W1 per-warp scratch early)
#define OFF_XW     20000      // 200*32  = 6400
#define OFF_SW     26400      // 4224 weight/scratch staging (W1^T = 32*132)
#define OFF_DINV   30624      // 200
#define OFF_ROWPTR 30824      // 204 ints
#define OFF_FILL   31028      // 200 ints
#define OFF_DEGI   31228      // 200 ints
#define OFF_CSRSRC 31428      // 6400 u16 -> 3200 slots
#define OFF_SRC16  34628      // 6400 u16 -> 3200 slots
#define OFF_DST16  37828      // 6400 u16 -> 3200 slots
#define OFF_KEY    41028      // 200
#define OFF_SEL    41228      // 32 ints
#define OFF_C1     41260      // 480
#define OFF_POOL   41740      // 240
#define OFF_FLAT   41980      // 352
#define OFF_HLIN   42332      // 128
#define SMEM_SLOTS 42460
#define SMEM_BYTES (SMEM_SLOTS * 4)

typedef unsigned long long u64;

__device__ __forceinline__ u64 fma2(u64 a, u64 b, u64 c) {
    u64 d; asm("fma.rn.f32x2 %0,%1,%2,%3;" : "=l"(d) : "l"(a), "l"(b), "l"(c)); return d;
}
__device__ __forceinline__ u64 add2(u64 a, u64 b) {
    u64 d; asm("add.rn.f32x2 %0,%1,%2;" : "=l"(d) : "l"(a), "l"(b)); return d;
}
__device__ __forceinline__ float2 u2f(u64 a) {
    float2 f; asm("mov.b64 {%0,%1},%2;" : "=f"(f.x), "=f"(f.y) : "l"(a)); return f;
}

__device__ __forceinline__ float warp_sum(float v) {
    #pragma unroll
    for (int o = 16; o > 0; o >>= 1) v += __shfl_down_sync(0xffffffffu, v, o);
    return v;
}

__device__ __forceinline__ float fast_tanh(float x) {
    float xc = fminf(fmaxf(x, -15.0f), 15.0f);
    float t = __expf(2.0f * xc);
    return __fdividef(t - 1.0f, t + 1.0f);
}

__global__ __launch_bounds__(NTHREADS, 1)
void dgcnn_kernel(
    const float* __restrict__ x, const int* __restrict__ ei,
    const float* __restrict__ W1, const float* __restrict__ b1,
    const float* __restrict__ W2, const float* __restrict__ b2,
    const float* __restrict__ W3, const float* __restrict__ b3,
    const float* __restrict__ W4, const float* __restrict__ b4,
    const float* __restrict__ convW1, const float* __restrict__ convb1,
    const float* __restrict__ convW2, const float* __restrict__ convb2,
    const float* __restrict__ linW1, const float* __restrict__ linb1,
    const float* __restrict__ linW2, const float* __restrict__ linb2,
    float* __restrict__ out)
{
    extern __shared__ float smem[];
    float* hcat   = smem + OFF_HCAT;    // [200][100]
    float* xw     = smem + OFF_XW;      // [200][32]
    float* sW     = smem + OFF_SW;      // transposed weight staging / scratch
    float* dinv   = smem + OFF_DINV;
    int*   rowptr = (int*)(smem + OFF_ROWPTR);
    int*   fill   = (int*)(smem + OFF_FILL);
    int*   degi   = (int*)(smem + OFF_DEGI);
    unsigned short* csrsrc = (unsigned short*)(smem + OFF_CSRSRC);
    unsigned short* src16  = (unsigned short*)(smem + OFF_SRC16);
    unsigned short* dst16  = (unsigned short*)(smem + OFF_DST16);
    float* sKey   = smem + OFF_KEY;
    int*   sSel   = (int*)(smem + OFF_SEL);
    float* sC1    = smem + OFF_C1;
    float* sPool  = smem + OFF_POOL;
    float* sFlat  = smem + OFF_FLAT;
    float* sHlin  = smem + OFF_HLIN;

    const int g    = blockIdx.x;
    const int tid  = threadIdx.x;
    const int lane = tid & 31;
    const int warp = tid >> 5;
    const int half = lane >> 4;      // 0/1: node of the pair (gather)
    const int hl   = lane & 15;      // feature-pair index within node
    const int nbase = g * MNODES;
    const long ebase = (long)g * EPG;
    const int* srcg = ei + ebase;
    const int* dstg = ei + (long)ETOT + ebase;

    // ================= Overlapped Phase A (CSR crew, warps 24-31) =================
    // ================= and Phase B (x@W1 crew, warps 0-23)        =================
    if (warp >= GEMM_WARPS) {
        const int ctid = tid - GEMM_WARPS * 32;   // 0..255
        for (int i = ctid; i < MNODES; i += 256) degi[i] = 0;
        asm volatile("bar.sync 1, 256;" ::: "memory");
        for (int i = ctid; i < EPG / 4; i += 256) {
            int4 s4 = ((const int4*)srcg)[i];
            int4 d4 = ((const int4*)dstg)[i];
            ushort4 ss, dd;
            ss.x = (unsigned short)(s4.x - nbase); ss.y = (unsigned short)(s4.y - nbase);
            ss.z = (unsigned short)(s4.z - nbase); ss.w = (unsigned short)(s4.w - nbase);
            dd.x = (unsigned short)(d4.x - nbase); dd.y = (unsigned short)(d4.y - nbase);
            dd.z = (unsigned short)(d4.z - nbase); dd.w = (unsigned short)(d4.w - nbase);
            ((ushort4*)src16)[i] = ss;
            ((ushort4*)dst16)[i] = dd;
            atomicAdd(&degi[dd.x], 1); atomicAdd(&degi[dd.y], 1);
            atomicAdd(&degi[dd.z], 1); atomicAdd(&degi[dd.w], 1);
        }
        asm volatile("bar.sync 1, 256;" ::: "memory");
        for (int i = ctid; i < MNODES; i += 256) {
            dinv[i] = rsqrtf((float)degi[i] + 1.0f);
            fill[i] = 0;
        }
        if (warp == GEMM_WARPS) {   // one warp does the scan
            int run = 0;
            #pragma unroll
            for (int c = 0; c < 7; ++c) {
                int i = c * 32 + lane;
                int dv = (i < MNODES) ? degi[i] : 0;
                int v = dv;
                #pragma unroll
                for (int o = 1; o < 32; o <<= 1) {
                    int t = __shfl_up_sync(0xffffffffu, v, o);
                    if (lane >= o) v += t;
                }
                if (i < MNODES) rowptr[i] = run + v - dv;
                run += __shfl_sync(0xffffffffu, v, 31);
            }
            if (lane == 0) rowptr[MNODES] = EPG;
        }
        asm volatile("bar.sync 1, 256;" ::: "memory");
        for (int i = ctid; i < EPG; i += 256) {
            int d = dst16[i];
            int pos = rowptr[d] + atomicAdd(&fill[d], 1);
            csrsrc[pos] = src16[i];
        }
    } else {
        // ---- x@W1 crew: stage W1^T (sW[c*132+k] = W1[k*32+c]), then GEMM ----
        for (int i = tid; i < 4096; i += GEMM_WARPS * 32) {
            int k = i >> 5, c = i & 31;
            sW[c * 132 + k] = W1[i];
        }
        asm volatile("bar.sync 2, 768;" ::: "memory");
        float* xs = hcat + warp * 528;      // per-warp scratch: 4 rows * 132
        const float* wrow = sW + lane * 132;
        for (int n0 = warp * 4; n0 < MNODES; n0 += GEMM_WARPS * 4) {
            #pragma unroll
            for (int j = 0; j < 4; ++j) {
                float4 v = *(const float4*)(x + (size_t)(nbase + n0 + j) * 128 + lane * 4);
                *(float4*)(xs + j * 132 + lane * 4) = v;
            }
            __syncwarp();
            u64 a00 = 0, a01 = 0, a10 = 0, a11 = 0, a20 = 0, a21 = 0, a30 = 0, a31 = 0;
            #pragma unroll 4
            for (int k = 0; k < 128; k += 4) {
                ulonglong2 wv = *(const ulonglong2*)(wrow + k);
                ulonglong2 h0 = *(const ulonglong2*)(xs + k);
                ulonglong2 h1 = *(const ulonglong2*)(xs + 132 + k);
                ulonglong2 h2 = *(const ulonglong2*)(xs + 264 + k);
                ulonglong2 h3 = *(const ulonglong2*)(xs + 396 + k);
                a00 = fma2(h0.x, wv.x, a00); a01 = fma2(h0.y, wv.y, a01);
                a10 = fma2(h1.x, wv.x, a10); a11 = fma2(h1.y, wv.y, a11);
                a20 = fma2(h2.x, wv.x, a20); a21 = fma2(h2.y, wv.y, a21);
                a30 = fma2(h3.x, wv.x, a30); a31 = fma2(h3.y, wv.y, a31);
            }
            // store UNscaled; dinv applied after join
            float2 r0 = u2f(add2(a00, a01)); xw[(n0 + 0) * 32 + lane] = r0.x + r0.y;
            float2 r1 = u2f(add2(a10, a11)); xw[(n0 + 1) * 32 + lane] = r1.x + r1.y;
            float2 r2 = u2f(add2(a20, a21)); xw[(n0 + 2) * 32 + lane] = r2.x + r2.y;
            float2 r3 = u2f(add2(a30, a31)); xw[(n0 + 3) * 32 + lane] = r3.x + r3.y;
            __syncwarp();
        }
    }
    __syncthreads();   // join crews

    // scale xw by dinv (same single multiply as before -> bit-identical)
    for (int i = tid; i < MNODES * 32; i += NTHREADS)
        xw[i] *= dinv[i >> 5];
    __syncthreads();

    // ---------------- GCN aggregation layers 1-3 (F=32) ----------------
    const float* Bv[3] = { b1, b2, b3 };
    const float* Wv[2] = { W2, W3 };
    for (int layer = 0; layer < 3; ++layer) {
        int off = layer * 32;
        float2 blv = *(const float2*)(Bv[layer] + 2 * hl);
        // gather: 2 nodes per warp (half-warps), float2 per lane, packed idx loads
        const float* xwh = xw + hl * 2;
        for (int p = warp; p < MNODES / 2; p += NW) {
            int node = p * 2 + half;
            int e0 = rowptr[node], e1 = rowptr[node + 1];
            u64 acc0 = *(const u64*)(xw + node * 32 + hl * 2);
            u64 acc1 = 0;
            int e = e0;
            if ((e & 1) && e < e1) {   // align to u32
                acc0 = add2(acc0, *(const u64*)(xwh + (int)csrsrc[e] * 32));
                ++e;
            }
            for (; e + 2 <= e1; e += 2) {
                unsigned pr = *(const unsigned*)(csrsrc + e);
                acc0 = add2(acc0, *(const u64*)(xwh + (int)(pr & 0xffffu) * 32));
                acc1 = add2(acc1, *(const u64*)(xwh + (int)(pr >> 16) * 32));
            }
            if (e < e1)
                acc1 = add2(acc1, *(const u64*)(xwh + (int)csrsrc[e] * 32));
            float2 a = u2f(add2(acc0, acc1));
            float dn = dinv[node];
            float* hp = hcat + node * 100 + off + hl * 2;
            hp[0] = fast_tanh(dn * a.x + blv.x);
            hp[1] = fast_tanh(dn * a.y + blv.y);
        }
        if (layer < 2) {
            for (int i = tid; i < 1024; i += NTHREADS) {
                int k = i >> 5, c = i & 31;
                sW[c * 36 + k] = Wv[layer][i];
            }
            __syncthreads();
            // xw_{l+1} = dinv * (h_l @ W), 4 nodes per warp
            const float* wrow = sW + lane * 36;
            for (int n0 = warp * 4; n0 < MNODES; n0 += NW * 4) {
                const float* hr0 = hcat + (n0 + 0) * 100 + off;
                const float* hr1 = hcat + (n0 + 1) * 100 + off;
                const float* hr2 = hcat + (n0 + 2) * 100 + off;
                const float* hr3 = hcat + (n0 + 3) * 100 + off;
                u64 a00 = 0, a01 = 0, a10 = 0, a11 = 0, a20 = 0, a21 = 0, a30 = 0, a31 = 0;
                #pragma unroll
                for (int k = 0; k < 32; k += 4) {
                    ulonglong2 wv = *(const ulonglong2*)(wrow + k);
                    ulonglong2 h0 = *(const ulonglong2*)(hr0 + k);
                    ulonglong2 h1 = *(const ulonglong2*)(hr1 + k);
                    ulonglong2 h2 = *(const ulonglong2*)(hr2 + k);
                    ulonglong2 h3 = *(const ulonglong2*)(hr3 + k);
                    a00 = fma2(h0.x, wv.x, a00); a01 = fma2(h0.y, wv.y, a01);
                    a10 = fma2(h1.x, wv.x, a10); a11 = fma2(h1.y, wv.y, a11);
                    a20 = fma2(h2.x, wv.x, a20); a21 = fma2(h2.y, wv.y, a21);
                    a30 = fma2(h3.x, wv.x, a30); a31 = fma2(h3.y, wv.y, a31);
                }
                float2 r0 = u2f(add2(a00, a01)); xw[(n0 + 0) * 32 + lane] = dinv[n0 + 0] * (r0.x + r0.y);
                float2 r1 = u2f(add2(a10, a11)); xw[(n0 + 1) * 32 + lane] = dinv[n0 + 1] * (r1.x + r1.y);
                float2 r2 = u2f(add2(a20, a21)); xw[(n0 + 2) * 32 + lane] = dinv[n0 + 2] * (r2.x + r2.y);
                float2 r3 = u2f(add2(a30, a31)); xw[(n0 + 3) * 32 + lane] = dinv[n0 + 3] * (r3.x + r3.y);
            }
            __syncthreads();
        } else {
            __syncthreads();
        }
    }

    // ---------------- Layer 4 (F=1) ----------------
    {
        float w4l = W4[lane];
        for (int n = warp; n < MNODES; n += NW) {
            float v = hcat[n * 100 + 64 + lane] * w4l;
            v = warp_sum(v);
            if (lane == 0) xw[n] = dinv[n] * v;   // xwd4[200]
        }
        __syncthreads();
        float b4v = b4[0];
        for (int n = tid; n < MNODES; n += NTHREADS) {
            float a0 = xw[n], a1 = 0.0f, a2 = 0.0f, a3 = 0.0f;
            int e = rowptr[n], e1 = rowptr[n + 1];
            for (; e + 4 <= e1; e += 4) {
                float v0 = xw[(int)csrsrc[e]];
                float v1 = xw[(int)csrsrc[e + 1]];
                float v2 = xw[(int)csrsrc[e + 2]];
                float v3 = xw[(int)csrsrc[e + 3]];
                a0 += v0; a1 += v1; a2 += v2; a3 += v3;
            }
            for (; e < e1; ++e) a1 += xw[(int)csrsrc[e]];
            float h4 = fast_tanh(dinv[n] * ((a0 + a2) + (a1 + a3)) + b4v);
            hcat[n * 100 + 96] = h4;
            sKey[n] = h4;
        }
        __syncthreads();
    }

    // ---------------- SortPool: stable top-30 by key desc (warp per node) ----------------
    for (int n = warp; n < MNODES; n += NW) {
        float ki = sKey[n];
        int cnt = 0;
        for (int j = lane; j < MNODES; j += 32) {
            float kj = sKey[j];
            cnt += (kj > ki) || (kj == ki && j < n);
        }
        cnt = __reduce_add_sync(0xffffffffu, cnt);
        if (lane == 0 && cnt < 30) sSel[cnt] = n;
    }
    for (int i = tid; i < 16 * 97; i += NTHREADS) sW[i] = convW1[i];
    for (int i = tid; i < 32 * 16 * 5; i += NTHREADS) sW[1552 + i] = convW2[i];
    __syncthreads();

    // ---------------- Conv1 (kernel 97, stride 97) -> [16][30], relu ----------------
    for (int it = warp; it < 480; it += NW) {
        int p = it / 16, oc = it % 16;
        int node = sSel[p];
        const float* hr = hcat + node * 100;
        const float* wr = sW + oc * 97;
        float v = hr[lane] * wr[lane] + hr[lane + 32] * wr[lane + 32]
                + hr[lane + 64] * wr[lane + 64];
        if (lane == 0) v += hr[96] * wr[96];
        v = warp_sum(v);
        if (lane == 0) sC1[oc * 30 + p] = fmaxf(v + convb1[oc], 0.0f);
    }
    __syncthreads();

    // ---------------- MaxPool1d(2,2) -> [16][15] ----------------
    for (int i = tid; i < 240; i += NTHREADS) {
        int oc = i / 15, t = i % 15;
        sPool[i] = fmaxf(sC1[oc * 30 + 2 * t], sC1[oc * 30 + 2 * t + 1]);
    }
    __syncthreads();

    // ---------------- Conv2 (16->32, k=5) -> [32][11], relu, flatten ----------------
    for (int it = tid; it < 352; it += NTHREADS) {
        int oc = it / 11, t = it % 11;
        float acc = convb2[oc];
        const float* w = sW + 1552 + oc * 80;
        #pragma unroll
        for (int ic = 0; ic < 16; ++ic) {
            #pragma unroll
            for (int k = 0; k < 5; ++k)
                acc += w[ic * 5 + k] * sPool[ic * 15 + t + k];
        }
        sFlat[oc * 11 + t] = fmaxf(acc, 0.0f);
    }
    __syncthreads();

    // ---------------- Linear 352->128 (split-K over 8 groups), relu ----------------
    {
        int grp = tid >> 7, t = tid & 127;
        float acc = 0.0f;
        int f0 = grp * 44, f1 = f0 + 44;
        for (int fi = f0; fi < f1; ++fi)
            acc += sFlat[fi] * linW1[fi * 128 + t];
        sW[grp * 128 + t] = acc;
    }
    __syncthreads();
    if (tid < 128) {
        float a = linb1[tid];
        #pragma unroll
        for (int grp = 0; grp < 8; ++grp) a += sW[grp * 128 + tid];
        sHlin[tid] = fmaxf(a, 0.0f);
    }
    __syncthreads();

    // ---------------- Linear 128->1, sigmoid ----------------
    if (warp == 0) {
        float acc = sHlin[lane] * linW2[lane] + sHlin[lane + 32] * linW2[lane + 32]
                  + sHlin[lane + 64] * linW2[lane + 64] + sHlin[lane + 96] * linW2[lane + 96];
        acc = warp_sum(acc);
        if (lane == 0) {
            float z = acc + linb2[0];
            out[g] = __fdividef(1.0f, 1.0f + __expf(-z));
        }
    }
}

extern "C" void kernel_launch(void* const* d_in, const int* in_sizes, int n_in,
                              void* d_out, int out_size) {
    const float* x      = (const float*)d_in[0];
    const int*   ei     = (const int*)  d_in[1];
    const float* W1     = (const float*)d_in[3];
    const float* b1     = (const float*)d_in[4];
    const float* W2     = (const float*)d_in[5];
    const float* b2     = (const float*)d_in[6];
    const float* W3     = (const float*)d_in[7];
    const float* b3     = (const float*)d_in[8];
    const float* W4     = (const float*)d_in[9];
    const float* b4     = (const float*)d_in[10];
    const float* convW1 = (const float*)d_in[11];
    const float* convb1 = (const float*)d_in[12];
    const float* convW2 = (const float*)d_in[13];
    const float* convb2 = (const float*)d_in[14];
    const float* linW1  = (const float*)d_in[15];
    const float* linb1  = (const float*)d_in[16];
    const float* linW2  = (const float*)d_in[17];
    const float* linb2  = (const float*)d_in[18];
    float* out = (float*)d_out;

    cudaFuncSetAttribute(dgcnn_kernel,
                         cudaFuncAttributeMaxDynamicSharedMemorySize, SMEM_BYTES);
    dgcnn_kernel<<<BGRAPHS, NTHREADS, SMEM_BYTES>>>(
        x, ei, W1, b1, W2, b2, W3, b3, W4, b4,
        convW1, convb1, convW2, convb2, linW1, linb1, linW2, linb2, out);
}